// round 1
// baseline (speedup 1.0000x reference)
#include <cuda_runtime.h>

#define Bn 64
#define Sn 1024
#define Xn 256
#define Yn 128

// ---------------- scratch (device globals: no cudaMalloc allowed) ----------
__device__ float g_Q[Bn * Sn * Yn];                 // 32 MB
__device__ float g_K[Bn * Sn * Yn];                 // 32 MB
__device__ float g_V[Bn * Sn * Yn];                 // 32 MB (becomes V/Z in place)
__device__ float g_Sc[(size_t)Bn * Sn * Sn];        // 256 MB scores [b][q][k]
__device__ float g_m[Bn * Sn];                      // per-(b,k) column max
__device__ float g_Zr[Bn * Sn];                     // per-(b,k) 1/sum
__device__ float g_O[Bn * Sn * Yn];                 // 32 MB pre-max output

// ============================================================================
// K1: QKV projection. C[m,n] = sum_x q[m,x] * W[n,x] + b[n]
// 128x128 tile, BK=16, 8x8 per thread, 256 threads. grid=(BS/128, 3)
// ============================================================================
__global__ __launch_bounds__(256, 2)
void qkv_kernel(const float* __restrict__ q,
                const float* __restrict__ Wq, const float* __restrict__ bq,
                const float* __restrict__ Wk, const float* __restrict__ bk,
                const float* __restrict__ Wv, const float* __restrict__ bv)
{
    const float* W; const float* bias; float* out;
    if (blockIdx.y == 0)      { W = Wq; bias = bq; out = g_Q; }
    else if (blockIdx.y == 1) { W = Wk; bias = bk; out = g_K; }
    else                      { W = Wv; bias = bv; out = g_V; }

    __shared__ float as[16][128];   // [k][m]
    __shared__ float ws[16][128];   // [k][n]

    const int tid = threadIdx.x;
    const int lr  = tid >> 1;           // loader row 0..127
    const int lc  = (tid & 1) * 8;      // loader col 0 or 8
    const int tx  = tid & 15;           // col group (8 cols)
    const int ty  = tid >> 4;           // row group (8 rows)
    const int rowBase = blockIdx.x * 128;

    float acc[8][8];
    #pragma unroll
    for (int i = 0; i < 8; i++)
        #pragma unroll
        for (int j = 0; j < 8; j++) acc[i][j] = 0.f;

    const float* Arow = q + (size_t)(rowBase + lr) * Xn;
    const float* Wrow = W + (size_t)lr * Xn;

    for (int kc = 0; kc < Xn; kc += 16) {
        float4 a0 = *(const float4*)(Arow + kc + lc);
        float4 a1 = *(const float4*)(Arow + kc + lc + 4);
        float4 w0 = *(const float4*)(Wrow + kc + lc);
        float4 w1 = *(const float4*)(Wrow + kc + lc + 4);
        as[lc+0][lr]=a0.x; as[lc+1][lr]=a0.y; as[lc+2][lr]=a0.z; as[lc+3][lr]=a0.w;
        as[lc+4][lr]=a1.x; as[lc+5][lr]=a1.y; as[lc+6][lr]=a1.z; as[lc+7][lr]=a1.w;
        ws[lc+0][lr]=w0.x; ws[lc+1][lr]=w0.y; ws[lc+2][lr]=w0.z; ws[lc+3][lr]=w0.w;
        ws[lc+4][lr]=w1.x; ws[lc+5][lr]=w1.y; ws[lc+6][lr]=w1.z; ws[lc+7][lr]=w1.w;
        __syncthreads();
        #pragma unroll
        for (int k = 0; k < 16; k++) {
            float4 ra0 = *(const float4*)&as[k][ty*8];
            float4 ra1 = *(const float4*)&as[k][ty*8+4];
            float4 rb0 = *(const float4*)&ws[k][tx*8];
            float4 rb1 = *(const float4*)&ws[k][tx*8+4];
            float ra[8] = {ra0.x,ra0.y,ra0.z,ra0.w,ra1.x,ra1.y,ra1.z,ra1.w};
            float rb[8] = {rb0.x,rb0.y,rb0.z,rb0.w,rb1.x,rb1.y,rb1.z,rb1.w};
            #pragma unroll
            for (int i = 0; i < 8; i++)
                #pragma unroll
                for (int j = 0; j < 8; j++)
                    acc[i][j] = fmaf(ra[i], rb[j], acc[i][j]);
        }
        __syncthreads();
    }

    #pragma unroll
    for (int i = 0; i < 8; i++) {
        float* orow = out + (size_t)(rowBase + ty*8 + i) * Yn;
        #pragma unroll
        for (int j = 0; j < 8; j += 4) {
            float4 v;
            v.x = acc[i][j+0] + bias[tx*8 + j + 0];
            v.y = acc[i][j+1] + bias[tx*8 + j + 1];
            v.z = acc[i][j+2] + bias[tx*8 + j + 2];
            v.w = acc[i][j+3] + bias[tx*8 + j + 3];
            *(float4*)(orow + tx*8 + j) = v;
        }
    }
}

// ============================================================================
// K2: scores S[b,q,k] = (1/sqrt(128)) * sum_d Q[b,q,d] * K[b,k,d]
// grid = (S/128, S/128, B)
// ============================================================================
__global__ __launch_bounds__(256, 2)
void scores_kernel()
{
    const int b  = blockIdx.z;
    const int qt = blockIdx.y;
    const int kt = blockIdx.x;

    const float* Qp = g_Q + (size_t)b * Sn * Yn;
    const float* Kp = g_K + (size_t)b * Sn * Yn;

    __shared__ float as[16][128];
    __shared__ float bs[16][128];

    const int tid = threadIdx.x;
    const int lr  = tid >> 1;
    const int lc  = (tid & 1) * 8;
    const int tx  = tid & 15;
    const int ty  = tid >> 4;

    float acc[8][8];
    #pragma unroll
    for (int i = 0; i < 8; i++)
        #pragma unroll
        for (int j = 0; j < 8; j++) acc[i][j] = 0.f;

    const float* Arow = Qp + (size_t)(qt*128 + lr) * Yn;
    const float* Brow = Kp + (size_t)(kt*128 + lr) * Yn;

    for (int kc = 0; kc < Yn; kc += 16) {
        float4 a0 = *(const float4*)(Arow + kc + lc);
        float4 a1 = *(const float4*)(Arow + kc + lc + 4);
        float4 b0 = *(const float4*)(Brow + kc + lc);
        float4 b1 = *(const float4*)(Brow + kc + lc + 4);
        as[lc+0][lr]=a0.x; as[lc+1][lr]=a0.y; as[lc+2][lr]=a0.z; as[lc+3][lr]=a0.w;
        as[lc+4][lr]=a1.x; as[lc+5][lr]=a1.y; as[lc+6][lr]=a1.z; as[lc+7][lr]=a1.w;
        bs[lc+0][lr]=b0.x; bs[lc+1][lr]=b0.y; bs[lc+2][lr]=b0.z; bs[lc+3][lr]=b0.w;
        bs[lc+4][lr]=b1.x; bs[lc+5][lr]=b1.y; bs[lc+6][lr]=b1.z; bs[lc+7][lr]=b1.w;
        __syncthreads();
        #pragma unroll
        for (int k = 0; k < 16; k++) {
            float4 ra0 = *(const float4*)&as[k][ty*8];
            float4 ra1 = *(const float4*)&as[k][ty*8+4];
            float4 rb0 = *(const float4*)&bs[k][tx*8];
            float4 rb1 = *(const float4*)&bs[k][tx*8+4];
            float ra[8] = {ra0.x,ra0.y,ra0.z,ra0.w,ra1.x,ra1.y,ra1.z,ra1.w};
            float rb[8] = {rb0.x,rb0.y,rb0.z,rb0.w,rb1.x,rb1.y,rb1.z,rb1.w};
            #pragma unroll
            for (int i = 0; i < 8; i++)
                #pragma unroll
                for (int j = 0; j < 8; j++)
                    acc[i][j] = fmaf(ra[i], rb[j], acc[i][j]);
        }
        __syncthreads();
    }

    const float scale = 0.08838834764831845f;  // 1/sqrt(128)
    float* Sp = g_Sc + (size_t)b * Sn * Sn;
    #pragma unroll
    for (int i = 0; i < 8; i++) {
        float* srow = Sp + (size_t)(qt*128 + ty*8 + i) * Sn + kt*128;
        #pragma unroll
        for (int j = 0; j < 8; j += 4) {
            float4 v;
            v.x = acc[i][j+0] * scale;
            v.y = acc[i][j+1] * scale;
            v.z = acc[i][j+2] * scale;
            v.w = acc[i][j+3] * scale;
            *(float4*)(srow + tx*8 + j) = v;
        }
    }
}

// ============================================================================
// K3: per-column (over q) max + sum-exp. grid = (S/256, B), 256 threads
// ============================================================================
__global__ void colstats_kernel()
{
    const int b = blockIdx.y;
    const int k = blockIdx.x * 256 + threadIdx.x;
    const float* Sp = g_Sc + (size_t)b * Sn * Sn;

    float m = -3.4e38f, z = 0.f;
    for (int q = 0; q < Sn; q += 4) {
        float sv[4];
        sv[0] = Sp[(size_t)(q+0)*Sn + k];
        sv[1] = Sp[(size_t)(q+1)*Sn + k];
        sv[2] = Sp[(size_t)(q+2)*Sn + k];
        sv[3] = Sp[(size_t)(q+3)*Sn + k];
        #pragma unroll
        for (int u = 0; u < 4; u++) {
            float s = sv[u];
            if (s <= m) {
                z += __expf(s - m);
            } else {
                z = z * __expf(m - s) + 1.0f;
                m = s;
            }
        }
    }
    g_m[b*Sn + k]  = m;
    g_Zr[b*Sn + k] = 1.0f / z;
}

// ============================================================================
// K3b: fold 1/Z into V rows (in place). grid = B*S*Y/256
// ============================================================================
__global__ void vnorm_kernel()
{
    const int i = blockIdx.x * 256 + threadIdx.x;
    g_V[i] *= g_Zr[i / Yn];
}

// ============================================================================
// K4: O[b,q,d] = sum_k exp(S[b,q,k] - m[b,k]) * Vn[b,k,d]
// exp applied while loading A tile. grid = (S/128, B)
// ============================================================================
__global__ __launch_bounds__(256, 2)
void pv_kernel()
{
    const int b  = blockIdx.y;
    const int qt = blockIdx.x;

    const float* Sp = g_Sc + (size_t)b * Sn * Sn;
    const float* Vp = g_V  + (size_t)b * Sn * Yn;
    const float* mp = g_m  + b * Sn;

    __shared__ float as[16][128];   // [k][q], holds exp(S - m)
    __shared__ float bs[16][128];   // [k][d]

    const int tid = threadIdx.x;
    const int lr  = tid >> 1;
    const int lc  = (tid & 1) * 8;
    const int tx  = tid & 15;
    const int ty  = tid >> 4;

    // B-tile loader mapping: 512 float4s per chunk, 2 per thread
    const int f0 = tid * 2;
    const int bk = f0 >> 5;           // k-row within chunk 0..15
    const int bd = (f0 & 31) * 4;     // d col 0..120 (even f0 -> bd <= 120)

    float acc[8][8];
    #pragma unroll
    for (int i = 0; i < 8; i++)
        #pragma unroll
        for (int j = 0; j < 8; j++) acc[i][j] = 0.f;

    const float* Arow = Sp + (size_t)(qt*128 + lr) * Sn;

    for (int kc = 0; kc < Sn; kc += 16) {
        float4 s0 = *(const float4*)(Arow + kc + lc);
        float4 s1 = *(const float4*)(Arow + kc + lc + 4);
        float4 m0 = *(const float4*)(mp + kc + lc);
        float4 m1 = *(const float4*)(mp + kc + lc + 4);
        as[lc+0][lr] = __expf(s0.x - m0.x);
        as[lc+1][lr] = __expf(s0.y - m0.y);
        as[lc+2][lr] = __expf(s0.z - m0.z);
        as[lc+3][lr] = __expf(s0.w - m0.w);
        as[lc+4][lr] = __expf(s1.x - m1.x);
        as[lc+5][lr] = __expf(s1.y - m1.y);
        as[lc+6][lr] = __expf(s1.z - m1.z);
        as[lc+7][lr] = __expf(s1.w - m1.w);

        const float* vrow = Vp + (size_t)(kc + bk) * Yn;
        float4 v0 = *(const float4*)(vrow + bd);
        float4 v1 = *(const float4*)(vrow + bd + 4);
        *(float4*)&bs[bk][bd]     = v0;
        *(float4*)&bs[bk][bd + 4] = v1;
        __syncthreads();
        #pragma unroll
        for (int k = 0; k < 16; k++) {
            float4 ra0 = *(const float4*)&as[k][ty*8];
            float4 ra1 = *(const float4*)&as[k][ty*8+4];
            float4 rb0 = *(const float4*)&bs[k][tx*8];
            float4 rb1 = *(const float4*)&bs[k][tx*8+4];
            float ra[8] = {ra0.x,ra0.y,ra0.z,ra0.w,ra1.x,ra1.y,ra1.z,ra1.w};
            float rb[8] = {rb0.x,rb0.y,rb0.z,rb0.w,rb1.x,rb1.y,rb1.z,rb1.w};
            #pragma unroll
            for (int i = 0; i < 8; i++)
                #pragma unroll
                for (int j = 0; j < 8; j++)
                    acc[i][j] = fmaf(ra[i], rb[j], acc[i][j]);
        }
        __syncthreads();
    }

    float* Op = g_O + (size_t)b * Sn * Yn;
    #pragma unroll
    for (int i = 0; i < 8; i++) {
        float* orow = Op + (size_t)(qt*128 + ty*8 + i) * Yn;
        #pragma unroll
        for (int j = 0; j < 8; j += 4) {
            float4 v;
            v.x = acc[i][j+0];
            v.y = acc[i][j+1];
            v.z = acc[i][j+2];
            v.w = acc[i][j+3];
            *(float4*)(orow + tx*8 + j) = v;
        }
    }
}

// ============================================================================
// K5: out[b,d] = max_q O[b,q,d]. grid = B, 128 threads
// ============================================================================
__global__ void maxout_kernel(float* __restrict__ out)
{
    const int b = blockIdx.x;
    const int d = threadIdx.x;
    const float* Op = g_O + (size_t)b * Sn * Yn;

    float m0 = -3.4e38f, m1 = -3.4e38f, m2 = -3.4e38f, m3 = -3.4e38f;
    for (int q = 0; q < Sn; q += 4) {
        m0 = fmaxf(m0, Op[(size_t)(q+0)*Yn + d]);
        m1 = fmaxf(m1, Op[(size_t)(q+1)*Yn + d]);
        m2 = fmaxf(m2, Op[(size_t)(q+2)*Yn + d]);
        m3 = fmaxf(m3, Op[(size_t)(q+3)*Yn + d]);
    }
    out[b*Yn + d] = fmaxf(fmaxf(m0, m1), fmaxf(m2, m3));
}

// ============================================================================
extern "C" void kernel_launch(void* const* d_in, const int* in_sizes, int n_in,
                              void* d_out, int out_size)
{
    const float* q  = (const float*)d_in[0];
    const float* Wq = (const float*)d_in[1];
    const float* bq = (const float*)d_in[2];
    const float* Wk = (const float*)d_in[3];
    const float* bk = (const float*)d_in[4];
    const float* Wv = (const float*)d_in[5];
    const float* bv = (const float*)d_in[6];
    float* out = (float*)d_out;

    qkv_kernel<<<dim3(Bn * Sn / 128, 3), 256>>>(q, Wq, bq, Wk, bk, Wv, bv);
    scores_kernel<<<dim3(Sn / 128, Sn / 128, Bn), 256>>>();
    colstats_kernel<<<dim3(Sn / 256, Bn), 256>>>();
    vnorm_kernel<<<(Bn * Sn * Yn) / 256, 256>>>();
    pv_kernel<<<dim3(Sn / 128, Bn), 256>>>();
    maxout_kernel<<<Bn, 128>>>(out);
}